// round 8
// baseline (speedup 1.0000x reference)
#include <cuda_runtime.h>
#include <cuda_bf16.h>
#include <math.h>
#include <stdint.h>

#define B_   4
#define C_   256
#define CI_  128
#define HW_  4096
#define MALL (B_*HW_)          // 16384
#define EPSbn 1e-5f

// ---------------- static scratch (no allocations allowed) ----------------
__device__ __nv_bfloat16 g_th[(size_t)MALL * CI_];      // theta hi [m][ci]
__device__ __nv_bfloat16 g_tl[(size_t)MALL * CI_];      // theta lo
__device__ __nv_bfloat16 g_phh[(size_t)MALL * CI_];     // phi hi
__device__ __nv_bfloat16 g_phl[(size_t)MALL * CI_];     // phi lo
__device__ __nv_bfloat16 g_gth[(size_t)B_ * CI_ * HW_]; // g^T hi [b][ci][hw]
__device__ __nv_bfloat16 g_gtl[(size_t)B_ * CI_ * HW_]; // g^T lo
__device__ __nv_bfloat16 g_yh[(size_t)MALL * CI_];      // y hi
__device__ __nv_bfloat16 g_yl[(size_t)MALL * CI_];      // y lo
__device__ __nv_bfloat16 g_owh[(size_t)C_ * CI_];       // out_w hi
__device__ __nv_bfloat16 g_owl[(size_t)C_ * CI_];       // out_w lo
__device__ float g_o[(size_t)MALL * C_];
__device__ float g_ps[2][256][256];
__device__ float g_scale[C_];
__device__ float g_shift[C_];

// ---------------- portable tensor-core helpers (sm_80+ PTX) ---------------
__device__ __forceinline__ uint32_t smem_u32(const void* p) {
    uint32_t a;
    asm("{ .reg .u64 t; cvta.to.shared.u64 t, %1; cvt.u32.u64 %0, t; }" : "=r"(a) : "l"(p));
    return a;
}
__device__ __forceinline__ void ldsm4(uint32_t* r, uint32_t addr) {
    asm volatile("ldmatrix.sync.aligned.m8n8.x4.shared.b16 {%0,%1,%2,%3}, [%4];"
        : "=r"(r[0]), "=r"(r[1]), "=r"(r[2]), "=r"(r[3]) : "r"(addr));
}
__device__ __forceinline__ void mma_bf16(float* c, const uint32_t* a, const uint32_t* b) {
    asm volatile(
        "mma.sync.aligned.m16n8k16.row.col.f32.bf16.bf16.f32 "
        "{%0,%1,%2,%3}, {%4,%5,%6,%7}, {%8,%9}, {%0,%1,%2,%3};"
        : "+f"(c[0]), "+f"(c[1]), "+f"(c[2]), "+f"(c[3])
        : "r"(a[0]), "r"(a[1]), "r"(a[2]), "r"(a[3]), "r"(b[0]), "r"(b[1]));
}
__device__ __forceinline__ void split1(float v, __nv_bfloat16& h, __nv_bfloat16& l) {
    h = __float2bfloat16(v);
    l = __float2bfloat16(v - __bfloat162float(h));
}
__device__ __forceinline__ uint32_t pack2(__nv_bfloat16 a, __nv_bfloat16 b) {
    __nv_bfloat162 v; v.x = a; v.y = b;
    return *(uint32_t*)&v;
}
__device__ __forceinline__ void cpa16(uint32_t dst, const void* src) {
    asm volatile("cp.async.cg.shared.global [%0], [%1], 16;" :: "r"(dst), "l"(src));
}
#define CP_COMMIT() asm volatile("cp.async.commit_group;" ::: "memory")
#define CP_WAIT0()  asm volatile("cp.async.wait_group 0;" ::: "memory")

// ---------------- kernel 1: projections -> bf16 hi/lo planes --------------
__global__ void proj_kernel(const float* __restrict__ x,
                            const float* __restrict__ gw,  const float* __restrict__ gb,
                            const float* __restrict__ tw,  const float* __restrict__ tb,
                            const float* __restrict__ pw,  const float* __restrict__ pb) {
    __shared__ float As[16][68];
    __shared__ float Bs[16][68];
    const int tid = threadIdx.x;
    const int n0 = blockIdx.x * 64;            // 0..383
    const int m0 = blockIdx.y * 64;
    const int b  = m0 / HW_;
    const int s0 = m0 % HW_;

    const float* wbase; const float* bbase; int j0;
    if      (n0 < 128) { wbase = gw; bbase = gb; j0 = n0;       }
    else if (n0 < 256) { wbase = tw; bbase = tb; j0 = n0 - 128; }
    else               { wbase = pw; bbase = pb; j0 = n0 - 256; }
    const int seg = n0 >> 7;

    const float* xb = x + (size_t)b * C_ * HW_;
    const int tx = tid & 15, ty = tid >> 4;
    float acc[4][4] = {};

    const int la_kk = tid >> 4, la_m4 = (tid & 15) * 4;
    const int lb_nn = tid >> 2, lb_k4 = (tid & 3) * 4;

    for (int k0 = 0; k0 < C_; k0 += 16) {
        float4 av = *(const float4*)&xb[(k0 + la_kk) * HW_ + s0 + la_m4];
        As[la_kk][la_m4+0] = av.x; As[la_kk][la_m4+1] = av.y;
        As[la_kk][la_m4+2] = av.z; As[la_kk][la_m4+3] = av.w;
        float4 bv = *(const float4*)&wbase[(j0 + lb_nn) * C_ + k0 + lb_k4];
        Bs[lb_k4+0][lb_nn] = bv.x; Bs[lb_k4+1][lb_nn] = bv.y;
        Bs[lb_k4+2][lb_nn] = bv.z; Bs[lb_k4+3][lb_nn] = bv.w;
        __syncthreads();
        #pragma unroll
        for (int kk = 0; kk < 16; kk++) {
            float a[4], bb[4];
            #pragma unroll
            for (int i = 0; i < 4; i++) a[i]  = As[kk][ty*4 + i];
            #pragma unroll
            for (int j = 0; j < 4; j++) bb[j] = Bs[kk][tx*4 + j];
            #pragma unroll
            for (int i = 0; i < 4; i++)
                #pragma unroll
                for (int j = 0; j < 4; j++) acc[i][j] += a[i] * bb[j];
        }
        __syncthreads();
    }

    if (seg == 0) {
        const int sl = (m0 - b * HW_) + ty * 4;
        #pragma unroll
        for (int jj = 0; jj < 4; jj++) {
            const int j = j0 + tx*4 + jj;
            union { __nv_bfloat16 h[4]; uint2 u; } H;
            union { __nv_bfloat16 l[4]; uint2 u; } L;
            #pragma unroll
            for (int i = 0; i < 4; i++) split1(acc[i][jj] + bbase[j], H.h[i], L.l[i]);
            const size_t dst = ((size_t)b * CI_ + j) * HW_ + sl;
            *(uint2*)&g_gth[dst] = H.u;
            *(uint2*)&g_gtl[dst] = L.u;
        }
    } else {
        __nv_bfloat16* ph = (seg == 1) ? g_th : g_phh;
        __nv_bfloat16* pl = (seg == 1) ? g_tl : g_phl;
        #pragma unroll
        for (int i = 0; i < 4; i++) {
            const int m = m0 + ty*4 + i;
            const int j = j0 + tx*4;
            union { __nv_bfloat16 h[4]; uint2 u; } H;
            union { __nv_bfloat16 l[4]; uint2 u; } L;
            #pragma unroll
            for (int jj = 0; jj < 4; jj++)
                split1(acc[i][jj] + bbase[j+jj], H.h[jj], L.l[jj]);
            *(uint2*)&ph[(size_t)m * CI_ + j] = H.u;
            *(uint2*)&pl[(size_t)m * CI_ + j] = L.u;
        }
    }
}

// ---------------- kernel 1b: out_w -> bf16 hi/lo --------------------------
__global__ void wconv_kernel(const float* __restrict__ ow) {
    const int i = blockIdx.x * 256 + threadIdx.x;   // 0..32767
    split1(ow[i], g_owh[i], g_owl[i]);
}

// ---------------- kernel 2: fused flash attention, register-resident P ----
#define ATT_SMEM 178688
__global__ __launch_bounds__(256, 1) void attn_fused() {
    extern __shared__ char sm[];
    const int t = threadIdx.x, w = t >> 5, l = t & 31;
    const int m0 = blockIdx.x * 64;
    const int b  = blockIdx.y;

    char* TH = sm;
    char* TL = sm + 17408;
    float* rsb = (float*)(sm + 178176);

    const size_t thbase = ((size_t)b * HW_ + m0) * CI_;
    const __nv_bfloat16* PhiH = g_phh + (size_t)b * HW_ * CI_;
    const __nv_bfloat16* PhiL = g_phl + (size_t)b * HW_ * CI_;
    const __nv_bfloat16* GHp  = g_gth + (size_t)b * CI_ * HW_;
    const __nv_bfloat16* GLp  = g_gtl + (size_t)b * CI_ * HW_;

    for (int i = t; i < 1024; i += 256) {
        const int row = i >> 4, c16 = i & 15;
        cpa16(smem_u32(TH + row*272 + c16*16), g_th + thbase + (size_t)row*CI_ + c16*8);
        cpa16(smem_u32(TL + row*272 + c16*16), g_tl + thbase + (size_t)row*CI_ + c16*8);
    }

    auto load_chunk = [&](int buf, int n0) {
        char* FH = sm + 34816 + buf * 34816;
        char* FL = FH + 17408;
        char* GS = sm + 104448 + buf * 36864;
        char* GSL = GS + 18432;
        for (int i = t; i < 1024; i += 256) {
            const int row = i >> 4, c16 = i & 15;
            const size_t so = (size_t)(n0 + row) * CI_ + c16 * 8;
            cpa16(smem_u32(FH + row*272 + c16*16), PhiH + so);
            cpa16(smem_u32(FL + row*272 + c16*16), PhiL + so);
        }
        for (int i = t; i < 1024; i += 256) {
            const int row = i >> 3, c16 = i & 7;
            const size_t so = (size_t)row * HW_ + n0 + c16 * 8;
            cpa16(smem_u32(GS  + row*144 + c16*16), GHp + so);
            cpa16(smem_u32(GSL + row*144 + c16*16), GLp + so);
        }
    };

    load_chunk(0, 0);
    CP_COMMIT();

    const int wm  = (w >> 1) * 16;       // warp row offset
    const int wns = (w & 1) * 32;        // warp key-half offset within chunk

    const int a_row = (l & 7) + ((l >> 3) & 1) * 8;
    const int a_kb  = (l >> 4) * 8;
    const int b_row = (l & 7) + (l >> 4) * 8;
    const int b_kb  = ((l >> 3) & 1) * 8;
    const int qr = l >> 2, qc = (l & 3) * 2;

    float Y[16][4];
    #pragma unroll
    for (int i = 0; i < 16; i++)
        #pragma unroll
        for (int j = 0; j < 4; j++) Y[i][j] = 0.f;
    float rs0 = 0.f, rs1 = 0.f;

    for (int c = 0; c < 64; c++) {
        const int cur = c & 1;
        CP_WAIT0();
        __syncthreads();
        if (c + 1 < 64) { load_chunk(cur ^ 1, (c + 1) * 64); CP_COMMIT(); }

        char* FH = sm + 34816 + cur * 34816;
        char* FL = FH + 17408;
        char* GS = sm + 104448 + cur * 36864;
        char* GSL = GS + 18432;

        // ---- S = theta . phi^T (bf16x3, 3 independent accumulator sets) --
        float Sa[4][4], Sb[4][4], Sc[4][4];
        #pragma unroll
        for (int i = 0; i < 4; i++)
            #pragma unroll
            for (int j = 0; j < 4; j++) { Sa[i][j] = 0.f; Sb[i][j] = 0.f; Sc[i][j] = 0.f; }

        #pragma unroll
        for (int ks = 0; ks < 8; ks++) {
            uint32_t aH[4], aL[4];
            const int aoff = (wm + a_row) * 272 + (ks*16 + a_kb) * 2;
            ldsm4(aH, smem_u32(TH + aoff));
            ldsm4(aL, smem_u32(TL + aoff));
            uint32_t bH[4][2], bL[4][2];
            #pragma unroll
            for (int q = 0; q < 2; q++) {
                const int boff = (wns + q*16 + b_row) * 272 + (ks*16 + b_kb) * 2;
                uint32_t r[4];
                ldsm4(r, smem_u32(FH + boff));
                bH[2*q][0] = r[0]; bH[2*q][1] = r[1];
                bH[2*q+1][0] = r[2]; bH[2*q+1][1] = r[3];
                ldsm4(r, smem_u32(FL + boff));
                bL[2*q][0] = r[0]; bL[2*q][1] = r[1];
                bL[2*q+1][0] = r[2]; bL[2*q+1][1] = r[3];
            }
            #pragma unroll
            for (int nf = 0; nf < 4; nf++) {
                mma_bf16(Sa[nf], aH, bH[nf]);
                mma_bf16(Sb[nf], aH, bL[nf]);
                mma_bf16(Sc[nf], aL, bH[nf]);
            }
        }

        // ---- combine + exp(s-20) + rowsum ----
        float S[4][4];
        #pragma unroll
        for (int nf = 0; nf < 4; nf++) {
            S[nf][0] = __expf((Sa[nf][0] + Sb[nf][0] + Sc[nf][0]) - 20.0f);
            S[nf][1] = __expf((Sa[nf][1] + Sb[nf][1] + Sc[nf][1]) - 20.0f);
            S[nf][2] = __expf((Sa[nf][2] + Sb[nf][2] + Sc[nf][2]) - 20.0f);
            S[nf][3] = __expf((Sa[nf][3] + Sb[nf][3] + Sc[nf][3]) - 20.0f);
            rs0 += S[nf][0] + S[nf][1];
            rs1 += S[nf][2] + S[nf][3];
        }

        // ---- Y += P . g  (A-frags from C-frags) ----
        #pragma unroll
        for (int ks = 0; ks < 2; ks++) {
            uint32_t aH[4], aL[4];
            {
                __nv_bfloat16 h0,l0,h1,l1;
                const float* s0 = S[2*ks];
                const float* s1 = S[2*ks+1];
                split1(s0[0], h0, l0); split1(s0[1], h1, l1);
                aH[0] = pack2(h0, h1); aL[0] = pack2(l0, l1);
                split1(s0[2], h0, l0); split1(s0[3], h1, l1);
                aH[1] = pack2(h0, h1); aL[1] = pack2(l0, l1);
                split1(s1[0], h0, l0); split1(s1[1], h1, l1);
                aH[2] = pack2(h0, h1); aL[2] = pack2(l0, l1);
                split1(s1[2], h0, l0); split1(s1[3], h1, l1);
                aH[3] = pack2(h0, h1); aL[3] = pack2(l0, l1);
            }
            const int kc = (wns + ks*16 + b_kb) * 2;
            #pragma unroll
            for (int q = 0; q < 8; q++) {
                const int boff = (q*16 + b_row) * 144 + kc;
                uint32_t rh[4], rl[4];
                ldsm4(rh, smem_u32(GS + boff));
                ldsm4(rl, smem_u32(GSL + boff));
                uint32_t bh0[2] = {rh[0], rh[1]}, bh1[2] = {rh[2], rh[3]};
                uint32_t bl0[2] = {rl[0], rl[1]}, bl1[2] = {rl[2], rl[3]};
                mma_bf16(Y[2*q],   aH, bh0);
                mma_bf16(Y[2*q],   aH, bl0);
                mma_bf16(Y[2*q],   aL, bh0);
                mma_bf16(Y[2*q+1], aH, bh1);
                mma_bf16(Y[2*q+1], aH, bl1);
                mma_bf16(Y[2*q+1], aL, bh1);
            }
        }
    }

    // ---- epilogue: rowsums, cross-key-half reduce, normalize, bf16 y ----
    rs0 += __shfl_xor_sync(0xffffffffu, rs0, 1);
    rs0 += __shfl_xor_sync(0xffffffffu, rs0, 2);
    rs1 += __shfl_xor_sync(0xffffffffu, rs1, 1);
    rs1 += __shfl_xor_sync(0xffffffffu, rs1, 2);
    if ((l & 3) == 0) {
        rsb[(wm + qr) * 2 + (w & 1)]     = rs0;
        rsb[(wm + qr + 8) * 2 + (w & 1)] = rs1;
    }
    __syncthreads();

    float* yst = (float*)(sm + 34816);   // 64 x 132 f32
    const int r0 = wm + qr, r1 = r0 + 8;
    if (w & 1) {
        #pragma unroll
        for (int nf = 0; nf < 16; nf++) {
            const int col = nf*8 + qc;
            *(float2*)(yst + r0*132 + col) = make_float2(Y[nf][0], Y[nf][1]);
            *(float2*)(yst + r1*132 + col) = make_float2(Y[nf][2], Y[nf][3]);
        }
    }
    __syncthreads();
    if (!(w & 1)) {
        const float ri0 = 1.0f / (rsb[r0*2] + rsb[r0*2+1]);
        const float ri1 = 1.0f / (rsb[r1*2] + rsb[r1*2+1]);
        const size_t yb = (size_t)b * HW_ + m0;
        #pragma unroll
        for (int nf = 0; nf < 16; nf++) {
            const int col = nf*8 + qc;
            float2 o0 = *(float2*)(yst + r0*132 + col);
            float2 o1 = *(float2*)(yst + r1*132 + col);
            float v00 = (Y[nf][0] + o0.x) * ri0, v01 = (Y[nf][1] + o0.y) * ri0;
            float v10 = (Y[nf][2] + o1.x) * ri1, v11 = (Y[nf][3] + o1.y) * ri1;
            __nv_bfloat16 h0,l0,h1,l1;
            split1(v00, h0, l0); split1(v01, h1, l1);
            *(uint32_t*)&g_yh[(yb + r0) * CI_ + col] = pack2(h0, h1);
            *(uint32_t*)&g_yl[(yb + r0) * CI_ + col] = pack2(l0, l1);
            split1(v10, h0, l0); split1(v11, h1, l1);
            *(uint32_t*)&g_yh[(yb + r1) * CI_ + col] = pack2(h0, h1);
            *(uint32_t*)&g_yl[(yb + r1) * CI_ + col] = pack2(l0, l1);
        }
    }
}

// ---------------- kernel 3: out conv via mma (bf16x3) ---------------------
// grid (2 n, 128 m), block 256 (8 warps, 4m x 2n of 32x64 warp tiles)
// o[m][n] = y[m][:].out_w[n][:] + ob[n]; K=128 single stage.
#define OC_PITCH 272
#define OC_PLANE (128 * OC_PITCH)   // 34816
__global__ __launch_bounds__(256, 1) void outconv_mma(const float* __restrict__ bias) {
    extern __shared__ char dsm[];
    const int t  = threadIdx.x;
    const int w  = t >> 5;
    const int l  = t & 31;
    const int m0 = blockIdx.y * 128;
    const int n0 = blockIdx.x * 128;

    char* Ah = dsm;
    char* Al = dsm + OC_PLANE;
    char* Bh = dsm + 2 * OC_PLANE;
    char* Bl = dsm + 3 * OC_PLANE;

    {
        const size_t ar = (size_t)m0 * CI_;
        const size_t br = (size_t)n0 * CI_;
        for (int i = t; i < 2048; i += 256) {
            const int row = i >> 4, c = i & 15;
            const size_t so = (size_t)row * CI_ + c * 8;
            const int dof = row * OC_PITCH + c * 16;
            cpa16(smem_u32(Ah + dof), g_yh  + ar + so);
            cpa16(smem_u32(Al + dof), g_yl  + ar + so);
            cpa16(smem_u32(Bh + dof), g_owh + br + so);
            cpa16(smem_u32(Bl + dof), g_owl + br + so);
        }
    }
    CP_COMMIT(); CP_WAIT0();
    __syncthreads();

    const int wm = (w >> 1) * 32;
    const int wn = (w & 1) * 64;

    float acc[2][8][4];
    #pragma unroll
    for (int i = 0; i < 2; i++)
        #pragma unroll
        for (int j = 0; j < 8; j++)
            #pragma unroll
            for (int k = 0; k < 4; k++) acc[i][j][k] = 0.f;

    const int a_row = (l & 7) + ((l >> 3) & 1) * 8;
    const int a_kb  = (l >> 4) * 8;
    const int b_row = (l & 7) + (l >> 4) * 8;
    const int b_kb  = ((l >> 3) & 1) * 8;

    #pragma unroll
    for (int ks = 0; ks < 8; ks++) {
        uint32_t aH[2][4], aL[2][4];
        #pragma unroll
        for (int mf = 0; mf < 2; mf++) {
            const int off = (wm + mf*16 + a_row) * OC_PITCH + (ks*16 + a_kb) * 2;
            ldsm4(aH[mf], smem_u32(Ah + off));
            ldsm4(aL[mf], smem_u32(Al + off));
        }
        uint32_t bH[8][2], bL[8][2];
        #pragma unroll
        for (int q = 0; q < 4; q++) {
            const int off = (wn + q*16 + b_row) * OC_PITCH + (ks*16 + b_kb) * 2;
            uint32_t r[4];
            ldsm4(r, smem_u32(Bh + off));
            bH[2*q][0] = r[0]; bH[2*q][1] = r[1]; bH[2*q+1][0] = r[2]; bH[2*q+1][1] = r[3];
            ldsm4(r, smem_u32(Bl + off));
            bL[2*q][0] = r[0]; bL[2*q][1] = r[1]; bL[2*q+1][0] = r[2]; bL[2*q+1][1] = r[3];
        }
        #pragma unroll
        for (int mf = 0; mf < 2; mf++)
            #pragma unroll
            for (int nf = 0; nf < 8; nf++) {
                mma_bf16(acc[mf][nf], aH[mf], bH[nf]);
                mma_bf16(acc[mf][nf], aH[mf], bL[nf]);
                mma_bf16(acc[mf][nf], aL[mf], bH[nf]);
            }
    }

    const int qr = l >> 2, qc = (l & 3) * 2;
    #pragma unroll
    for (int mf = 0; mf < 2; mf++) {
        const int r0 = m0 + wm + mf*16 + qr;
        const int r1 = r0 + 8;
        #pragma unroll
        for (int nf = 0; nf < 8; nf++) {
            const int col = n0 + wn + nf*8 + qc;
            const float b0 = bias[col], b1 = bias[col+1];
            *(float2*)&g_o[(size_t)r0 * C_ + col] =
                make_float2(acc[mf][nf][0] + b0, acc[mf][nf][1] + b1);
            *(float2*)&g_o[(size_t)r1 * C_ + col] =
                make_float2(acc[mf][nf][2] + b0, acc[mf][nf][3] + b1);
        }
    }
}

// ---------------- BN stats ------------------------------------------------
__global__ void stats1_kernel() {
    const int chunk = blockIdx.x;
    const int c = threadIdx.x;
    float s = 0.f, ss = 0.f;
    const float* p = g_o + (size_t)chunk * 64 * C_ + c;
    #pragma unroll 4
    for (int r = 0; r < 64; r++) {
        float v = p[(size_t)r * C_];
        s += v; ss += v * v;
    }
    g_ps[0][chunk][c] = s;
    g_ps[1][chunk][c] = ss;
}

__global__ void stats2_kernel(const float* __restrict__ gamma,
                              const float* __restrict__ beta) {
    const int c = threadIdx.x;
    float s = 0.f, ss = 0.f;
    for (int k = 0; k < 256; k++) { s += g_ps[0][k][c]; ss += g_ps[1][k][c]; }
    const float inv_n = 1.0f / (float)MALL;
    float mean = s * inv_n;
    float var  = ss * inv_n - mean * mean;
    float sc = gamma[c] * rsqrtf(var + EPSbn);
    g_scale[c] = sc;
    g_shift[c] = beta[c] - mean * sc;
}

// ---------------- BN apply + ReLU + residual ------------------------------
__global__ void final_kernel(const float* __restrict__ x, float* __restrict__ out) {
    __shared__ float tile[64][65];
    const int s0 = blockIdx.x * 64;
    const int c0 = blockIdx.y * 64;
    const int b  = blockIdx.z;
    const int t  = threadIdx.x;

    const int lr = t >> 2, lc = (t & 3) * 16;
    #pragma unroll
    for (int q = 0; q < 4; q++) {
        float4 v = *(const float4*)&g_o[(size_t)(b*HW_ + s0 + lr) * C_ + c0 + lc + q*4];
        tile[lr][lc + q*4 + 0] = v.x; tile[lr][lc + q*4 + 1] = v.y;
        tile[lr][lc + q*4 + 2] = v.z; tile[lr][lc + q*4 + 3] = v.w;
    }
    __syncthreads();

    const int cl = t >> 2, sg = (t & 3) * 16;
    const int c = c0 + cl;
    const float sc = g_scale[c], sh = g_shift[c];
    const size_t base = ((size_t)b * C_ + c) * HW_ + s0 + sg;
    #pragma unroll
    for (int q = 0; q < 4; q++) {
        float4 xv = *(const float4*)&x[base + q*4];
        float4 w;
        w.x = fmaxf(tile[sg + q*4 + 0][cl] * sc + sh, 0.f) + xv.x;
        w.y = fmaxf(tile[sg + q*4 + 1][cl] * sc + sh, 0.f) + xv.y;
        w.z = fmaxf(tile[sg + q*4 + 2][cl] * sc + sh, 0.f) + xv.z;
        w.w = fmaxf(tile[sg + q*4 + 3][cl] * sc + sh, 0.f) + xv.w;
        *(float4*)&out[base + q*4] = w;
    }
}

// ---------------- launch ---------------------------------------------------
extern "C" void kernel_launch(void* const* d_in, const int* in_sizes, int n_in,
                              void* d_out, int out_size) {
    const float* x     = (const float*)d_in[0];
    const float* gw    = (const float*)d_in[1];
    const float* gb    = (const float*)d_in[2];
    const float* tw    = (const float*)d_in[3];
    const float* tb    = (const float*)d_in[4];
    const float* pw    = (const float*)d_in[5];
    const float* pb    = (const float*)d_in[6];
    const float* ow    = (const float*)d_in[7];
    const float* ob    = (const float*)d_in[8];
    const float* gamma = (const float*)d_in[9];
    const float* beta  = (const float*)d_in[10];
    float* out = (float*)d_out;

    cudaFuncSetAttribute(attn_fused,  cudaFuncAttributeMaxDynamicSharedMemorySize, ATT_SMEM);
    cudaFuncSetAttribute(outconv_mma, cudaFuncAttributeMaxDynamicSharedMemorySize, 4 * OC_PLANE);

    proj_kernel    <<<dim3(6, 256),   256>>>(x, gw, gb, tw, tb, pw, pb);
    wconv_kernel   <<<dim3(128),      256>>>(ow);
    attn_fused     <<<dim3(64, 4),    256, ATT_SMEM>>>();
    outconv_mma    <<<dim3(2, 128),   256, 4 * OC_PLANE>>>(ob);
    stats1_kernel  <<<dim3(256),      256>>>();
    stats2_kernel  <<<dim3(1),        256>>>(gamma, beta);
    final_kernel   <<<dim3(64, 4, 4), 256>>>(x, out);
}

// round 9
// speedup vs baseline: 1.0633x; 1.0633x over previous
#include <cuda_runtime.h>
#include <cuda_bf16.h>
#include <math.h>
#include <stdint.h>

#define B_   4
#define C_   256
#define CI_  128
#define HW_  4096
#define MALL (B_*HW_)          // 16384
#define EPSbn 1e-5f

// ---------------- static scratch (no allocations allowed) ----------------
__device__ __nv_bfloat16 g_th[(size_t)MALL * CI_];      // theta hi [m][ci]
__device__ __nv_bfloat16 g_tl[(size_t)MALL * CI_];      // theta lo
__device__ __nv_bfloat16 g_phh[(size_t)MALL * CI_];     // phi hi
__device__ __nv_bfloat16 g_phl[(size_t)MALL * CI_];     // phi lo
__device__ __nv_bfloat16 g_gh[(size_t)MALL * CI_];      // g hi [m][ci]
__device__ __nv_bfloat16 g_gl[(size_t)MALL * CI_];      // g lo
__device__ __nv_bfloat16 g_yh[(size_t)MALL * CI_];      // y hi
__device__ __nv_bfloat16 g_yl[(size_t)MALL * CI_];      // y lo
__device__ __nv_bfloat16 g_owh[(size_t)C_ * CI_];       // out_w hi
__device__ __nv_bfloat16 g_owl[(size_t)C_ * CI_];       // out_w lo
__device__ float g_o[(size_t)MALL * C_];
__device__ float g_ps[2][256][256];
__device__ float g_scale[C_];
__device__ float g_shift[C_];

// ---------------- portable tensor-core helpers (sm_80+ PTX) ---------------
__device__ __forceinline__ uint32_t smem_u32(const void* p) {
    uint32_t a;
    asm("{ .reg .u64 t; cvta.to.shared.u64 t, %1; cvt.u32.u64 %0, t; }" : "=r"(a) : "l"(p));
    return a;
}
__device__ __forceinline__ void ldsm4(uint32_t* r, uint32_t addr) {
    asm volatile("ldmatrix.sync.aligned.m8n8.x4.shared.b16 {%0,%1,%2,%3}, [%4];"
        : "=r"(r[0]), "=r"(r[1]), "=r"(r[2]), "=r"(r[3]) : "r"(addr));
}
__device__ __forceinline__ void ldsm4t(uint32_t* r, uint32_t addr) {
    asm volatile("ldmatrix.sync.aligned.m8n8.x4.trans.shared.b16 {%0,%1,%2,%3}, [%4];"
        : "=r"(r[0]), "=r"(r[1]), "=r"(r[2]), "=r"(r[3]) : "r"(addr));
}
__device__ __forceinline__ void mma_bf16(float* c, const uint32_t* a, const uint32_t* b) {
    asm volatile(
        "mma.sync.aligned.m16n8k16.row.col.f32.bf16.bf16.f32 "
        "{%0,%1,%2,%3}, {%4,%5,%6,%7}, {%8,%9}, {%0,%1,%2,%3};"
        : "+f"(c[0]), "+f"(c[1]), "+f"(c[2]), "+f"(c[3])
        : "r"(a[0]), "r"(a[1]), "r"(a[2]), "r"(a[3]), "r"(b[0]), "r"(b[1]));
}
__device__ __forceinline__ void split1(float v, __nv_bfloat16& h, __nv_bfloat16& l) {
    h = __float2bfloat16(v);
    l = __float2bfloat16(v - __bfloat162float(h));
}
__device__ __forceinline__ uint32_t pack2(__nv_bfloat16 a, __nv_bfloat16 b) {
    __nv_bfloat162 v; v.x = a; v.y = b;
    return *(uint32_t*)&v;
}
__device__ __forceinline__ void cpa16(uint32_t dst, const void* src) {
    asm volatile("cp.async.cg.shared.global [%0], [%1], 16;" :: "r"(dst), "l"(src));
}
#define CP_COMMIT() asm volatile("cp.async.commit_group;" ::: "memory")
#define CP_WAIT0()  asm volatile("cp.async.wait_group 0;" ::: "memory")

// ---------------- kernel 1: projections -> bf16 hi/lo planes [m][ci] ------
__global__ void proj_kernel(const float* __restrict__ x,
                            const float* __restrict__ gw,  const float* __restrict__ gb,
                            const float* __restrict__ tw,  const float* __restrict__ tb,
                            const float* __restrict__ pw,  const float* __restrict__ pb) {
    __shared__ float As[16][68];
    __shared__ float Bs[16][68];
    const int tid = threadIdx.x;
    const int n0 = blockIdx.x * 64;            // 0..383
    const int m0 = blockIdx.y * 64;
    const int b  = m0 / HW_;
    const int s0 = m0 % HW_;

    const float* wbase; const float* bbase; int j0;
    if      (n0 < 128) { wbase = gw; bbase = gb; j0 = n0;       }
    else if (n0 < 256) { wbase = tw; bbase = tb; j0 = n0 - 128; }
    else               { wbase = pw; bbase = pb; j0 = n0 - 256; }
    const int seg = n0 >> 7;

    const float* xb = x + (size_t)b * C_ * HW_;
    const int tx = tid & 15, ty = tid >> 4;
    float acc[4][4] = {};

    const int la_kk = tid >> 4, la_m4 = (tid & 15) * 4;
    const int lb_nn = tid >> 2, lb_k4 = (tid & 3) * 4;

    for (int k0 = 0; k0 < C_; k0 += 16) {
        float4 av = *(const float4*)&xb[(k0 + la_kk) * HW_ + s0 + la_m4];
        As[la_kk][la_m4+0] = av.x; As[la_kk][la_m4+1] = av.y;
        As[la_kk][la_m4+2] = av.z; As[la_kk][la_m4+3] = av.w;
        float4 bv = *(const float4*)&wbase[(j0 + lb_nn) * C_ + k0 + lb_k4];
        Bs[lb_k4+0][lb_nn] = bv.x; Bs[lb_k4+1][lb_nn] = bv.y;
        Bs[lb_k4+2][lb_nn] = bv.z; Bs[lb_k4+3][lb_nn] = bv.w;
        __syncthreads();
        #pragma unroll
        for (int kk = 0; kk < 16; kk++) {
            float a[4], bb[4];
            #pragma unroll
            for (int i = 0; i < 4; i++) a[i]  = As[kk][ty*4 + i];
            #pragma unroll
            for (int j = 0; j < 4; j++) bb[j] = Bs[kk][tx*4 + j];
            #pragma unroll
            for (int i = 0; i < 4; i++)
                #pragma unroll
                for (int j = 0; j < 4; j++) acc[i][j] += a[i] * bb[j];
        }
        __syncthreads();
    }

    __nv_bfloat16* ph = (seg == 0) ? g_gh : ((seg == 1) ? g_th : g_phh);
    __nv_bfloat16* pl = (seg == 0) ? g_gl : ((seg == 1) ? g_tl : g_phl);
    #pragma unroll
    for (int i = 0; i < 4; i++) {
        const int m = m0 + ty*4 + i;
        const int j = j0 + tx*4;
        union { __nv_bfloat16 h[4]; uint2 u; } H;
        union { __nv_bfloat16 l[4]; uint2 u; } L;
        #pragma unroll
        for (int jj = 0; jj < 4; jj++)
            split1(acc[i][jj] + bbase[j+jj], H.h[jj], L.l[jj]);
        *(uint2*)&ph[(size_t)m * CI_ + j] = H.u;
        *(uint2*)&pl[(size_t)m * CI_ + j] = L.u;
    }
}

// ---------------- kernel 1b: out_w -> bf16 hi/lo --------------------------
__global__ void wconv_kernel(const float* __restrict__ ow) {
    const int i = blockIdx.x * 256 + threadIdx.x;   // 0..32767
    split1(ow[i], g_owh[i], g_owl[i]);
}

// ---------------- kernel 2: fused flash attention, 4 warps, 2 CTA/SM ------
// grid (64 m-tiles, 4 b), block 128. Each CTA: 64 query rows.
// Warp w: rows w*16..+16, full 128 ci, all keys. Chunk = 32 keys, 128 chunks.
// smem: theta hi/lo 0..34816 (pitch 272);
//       buf k at 34816 + k*34816: FH(8704) FL GH GL (each 32x272=8704)
#define ATT_SMEM 104448
__global__ __launch_bounds__(128, 2) void attn_fused() {
    extern __shared__ char sm[];
    const int t = threadIdx.x, w = t >> 5, l = t & 31;
    const int m0 = blockIdx.x * 64;
    const int b  = blockIdx.y;

    char* TH = sm;
    char* TL = sm + 17408;

    const size_t thbase = ((size_t)b * HW_ + m0) * CI_;
    const __nv_bfloat16* PhiH = g_phh + (size_t)b * HW_ * CI_;
    const __nv_bfloat16* PhiL = g_phl + (size_t)b * HW_ * CI_;
    const __nv_bfloat16* GHp  = g_gh  + (size_t)b * HW_ * CI_;
    const __nv_bfloat16* GLp  = g_gl  + (size_t)b * HW_ * CI_;

    // theta: 64 rows x 16 c16 x 2 planes
    for (int i = t; i < 1024; i += 128) {
        const int row = i >> 4, c16 = i & 15;
        cpa16(smem_u32(TH + row*272 + c16*16), g_th + thbase + (size_t)row*CI_ + c16*8);
        cpa16(smem_u32(TL + row*272 + c16*16), g_tl + thbase + (size_t)row*CI_ + c16*8);
    }

    auto load_chunk = [&](int buf, int n0) {
        char* base = sm + 34816 + buf * 34816;
        for (int i = t; i < 512; i += 128) {
            const int row = i >> 4, c16 = i & 15;
            const size_t so = (size_t)(n0 + row) * CI_ + c16 * 8;
            const int dof = row*272 + c16*16;
            cpa16(smem_u32(base +         dof), PhiH + so);
            cpa16(smem_u32(base +  8704 + dof), PhiL + so);
            cpa16(smem_u32(base + 17408 + dof), GHp + so);
            cpa16(smem_u32(base + 26112 + dof), GLp + so);
        }
    };

    load_chunk(0, 0);
    CP_COMMIT();

    const int wm = w * 16;

    const int a_row = (l & 7) + ((l >> 3) & 1) * 8;
    const int a_kb  = (l >> 4) * 8;
    const int b_row = (l & 7) + (l >> 4) * 8;
    const int b_kb  = ((l >> 3) & 1) * 8;
    // trans-ldsm lane map (g stored [key][ci]): row=key part, col=ci part
    const int y_row = (l & 7) + ((l >> 3) & 1) * 8;
    const int y_cb  = (l >> 4) * 8;
    const int qr = l >> 2, qc = (l & 3) * 2;

    float Y[16][4];
    #pragma unroll
    for (int i = 0; i < 16; i++)
        #pragma unroll
        for (int j = 0; j < 4; j++) Y[i][j] = 0.f;
    float rs0 = 0.f, rs1 = 0.f;

    for (int c = 0; c < 128; c++) {
        const int cur = c & 1;
        CP_WAIT0();
        __syncthreads();
        if (c + 1 < 128) { load_chunk(cur ^ 1, (c + 1) * 32); CP_COMMIT(); }

        char* FH = sm + 34816 + cur * 34816;
        char* FL = FH + 8704;
        char* GS = FH + 17408;
        char* GSL = FH + 26112;

        // ---- S = theta . phi^T (16 rows x 32 keys, K=128, bf16x3) ----
        float S[4][4];
        #pragma unroll
        for (int i = 0; i < 4; i++)
            #pragma unroll
            for (int j = 0; j < 4; j++) S[i][j] = 0.f;

        #pragma unroll
        for (int ks = 0; ks < 8; ks++) {
            uint32_t aH[4], aL[4];
            const int aoff = (wm + a_row) * 272 + (ks*16 + a_kb) * 2;
            ldsm4(aH, smem_u32(TH + aoff));
            ldsm4(aL, smem_u32(TL + aoff));
            uint32_t bH[4][2], bL[4][2];
            #pragma unroll
            for (int q = 0; q < 2; q++) {
                const int boff = (q*16 + b_row) * 272 + (ks*16 + b_kb) * 2;
                uint32_t r[4];
                ldsm4(r, smem_u32(FH + boff));
                bH[2*q][0] = r[0]; bH[2*q][1] = r[1];
                bH[2*q+1][0] = r[2]; bH[2*q+1][1] = r[3];
                ldsm4(r, smem_u32(FL + boff));
                bL[2*q][0] = r[0]; bL[2*q][1] = r[1];
                bL[2*q+1][0] = r[2]; bL[2*q+1][1] = r[3];
            }
            #pragma unroll
            for (int nf = 0; nf < 4; nf++) {
                mma_bf16(S[nf], aH, bH[nf]);
                mma_bf16(S[nf], aH, bL[nf]);
                mma_bf16(S[nf], aL, bH[nf]);
            }
        }

        // ---- exp(s-20) in regs + rowsum ----
        #pragma unroll
        for (int nf = 0; nf < 4; nf++) {
            S[nf][0] = __expf(S[nf][0] - 20.0f);
            S[nf][1] = __expf(S[nf][1] - 20.0f);
            S[nf][2] = __expf(S[nf][2] - 20.0f);
            S[nf][3] = __expf(S[nf][3] - 20.0f);
            rs0 += S[nf][0] + S[nf][1];
            rs1 += S[nf][2] + S[nf][3];
        }

        // ---- Y += P . g  (K = 32 keys, A-frags from C-frags; trans B) ----
        #pragma unroll
        for (int ks = 0; ks < 2; ks++) {
            uint32_t aH[4], aL[4];
            {
                __nv_bfloat16 h0,l0,h1,l1;
                const float* s0 = S[2*ks];
                const float* s1 = S[2*ks+1];
                split1(s0[0], h0, l0); split1(s0[1], h1, l1);
                aH[0] = pack2(h0, h1); aL[0] = pack2(l0, l1);
                split1(s0[2], h0, l0); split1(s0[3], h1, l1);
                aH[1] = pack2(h0, h1); aL[1] = pack2(l0, l1);
                split1(s1[0], h0, l0); split1(s1[1], h1, l1);
                aH[2] = pack2(h0, h1); aL[2] = pack2(l0, l1);
                split1(s1[2], h0, l0); split1(s1[3], h1, l1);
                aH[3] = pack2(h0, h1); aL[3] = pack2(l0, l1);
            }
            #pragma unroll
            for (int q = 0; q < 8; q++) {
                const int boff = (ks*16 + y_row) * 272 + (q*16 + y_cb) * 2;
                uint32_t rh[4], rl[4];
                ldsm4t(rh, smem_u32(GS + boff));
                ldsm4t(rl, smem_u32(GSL + boff));
                uint32_t bh0[2] = {rh[0], rh[1]}, bh1[2] = {rh[2], rh[3]};
                uint32_t bl0[2] = {rl[0], rl[1]}, bl1[2] = {rl[2], rl[3]};
                mma_bf16(Y[2*q],   aH, bh0);
                mma_bf16(Y[2*q],   aH, bl0);
                mma_bf16(Y[2*q],   aL, bh0);
                mma_bf16(Y[2*q+1], aH, bh1);
                mma_bf16(Y[2*q+1], aH, bl1);
                mma_bf16(Y[2*q+1], aL, bh1);
            }
        }
    }

    // ---- epilogue: quad rowsum reduce, normalize, bf16 hi/lo y ----
    rs0 += __shfl_xor_sync(0xffffffffu, rs0, 1);
    rs0 += __shfl_xor_sync(0xffffffffu, rs0, 2);
    rs1 += __shfl_xor_sync(0xffffffffu, rs1, 1);
    rs1 += __shfl_xor_sync(0xffffffffu, rs1, 2);
    const float ri0 = 1.0f / rs0;
    const float ri1 = 1.0f / rs1;

    const size_t yb = (size_t)b * HW_ + m0;
    const int r0 = wm + qr, r1 = r0 + 8;
    #pragma unroll
    for (int nf = 0; nf < 16; nf++) {
        const int col = nf*8 + qc;
        float v00 = Y[nf][0] * ri0, v01 = Y[nf][1] * ri0;
        float v10 = Y[nf][2] * ri1, v11 = Y[nf][3] * ri1;
        __nv_bfloat16 h0,l0,h1,l1;
        split1(v00, h0, l0); split1(v01, h1, l1);
        *(uint32_t*)&g_yh[(yb + r0) * CI_ + col] = pack2(h0, h1);
        *(uint32_t*)&g_yl[(yb + r0) * CI_ + col] = pack2(l0, l1);
        split1(v10, h0, l0); split1(v11, h1, l1);
        *(uint32_t*)&g_yh[(yb + r1) * CI_ + col] = pack2(h0, h1);
        *(uint32_t*)&g_yl[(yb + r1) * CI_ + col] = pack2(l0, l1);
    }
}

// ---------------- kernel 3: out conv via mma (bf16x3) ---------------------
#define OC_PITCH 272
#define OC_PLANE (128 * OC_PITCH)   // 34816
__global__ __launch_bounds__(256, 1) void outconv_mma(const float* __restrict__ bias) {
    extern __shared__ char dsm[];
    const int t  = threadIdx.x;
    const int w  = t >> 5;
    const int l  = t & 31;
    const int m0 = blockIdx.y * 128;
    const int n0 = blockIdx.x * 128;

    char* Ah = dsm;
    char* Al = dsm + OC_PLANE;
    char* Bh = dsm + 2 * OC_PLANE;
    char* Bl = dsm + 3 * OC_PLANE;

    {
        const size_t ar = (size_t)m0 * CI_;
        const size_t br = (size_t)n0 * CI_;
        for (int i = t; i < 2048; i += 256) {
            const int row = i >> 4, c = i & 15;
            const size_t so = (size_t)row * CI_ + c * 8;
            const int dof = row * OC_PITCH + c * 16;
            cpa16(smem_u32(Ah + dof), g_yh  + ar + so);
            cpa16(smem_u32(Al + dof), g_yl  + ar + so);
            cpa16(smem_u32(Bh + dof), g_owh + br + so);
            cpa16(smem_u32(Bl + dof), g_owl + br + so);
        }
    }
    CP_COMMIT(); CP_WAIT0();
    __syncthreads();

    const int wm = (w >> 1) * 32;
    const int wn = (w & 1) * 64;

    float acc[2][8][4];
    #pragma unroll
    for (int i = 0; i < 2; i++)
        #pragma unroll
        for (int j = 0; j < 8; j++)
            #pragma unroll
            for (int k = 0; k < 4; k++) acc[i][j][k] = 0.f;

    const int a_row = (l & 7) + ((l >> 3) & 1) * 8;
    const int a_kb  = (l >> 4) * 8;
    const int b_row = (l & 7) + (l >> 4) * 8;
    const int b_kb  = ((l >> 3) & 1) * 8;

    #pragma unroll
    for (int ks = 0; ks < 8; ks++) {
        uint32_t aH[2][4], aL[2][4];
        #pragma unroll
        for (int mf = 0; mf < 2; mf++) {
            const int off = (wm + mf*16 + a_row) * OC_PITCH + (ks*16 + a_kb) * 2;
            ldsm4(aH[mf], smem_u32(Ah + off));
            ldsm4(aL[mf], smem_u32(Al + off));
        }
        uint32_t bH[8][2], bL[8][2];
        #pragma unroll
        for (int q = 0; q < 4; q++) {
            const int off = (wn + q*16 + b_row) * OC_PITCH + (ks*16 + b_kb) * 2;
            uint32_t r[4];
            ldsm4(r, smem_u32(Bh + off));
            bH[2*q][0] = r[0]; bH[2*q][1] = r[1]; bH[2*q+1][0] = r[2]; bH[2*q+1][1] = r[3];
            ldsm4(r, smem_u32(Bl + off));
            bL[2*q][0] = r[0]; bL[2*q][1] = r[1]; bL[2*q+1][0] = r[2]; bL[2*q+1][1] = r[3];
        }
        #pragma unroll
        for (int mf = 0; mf < 2; mf++)
            #pragma unroll
            for (int nf = 0; nf < 8; nf++) {
                mma_bf16(acc[mf][nf], aH[mf], bH[nf]);
                mma_bf16(acc[mf][nf], aH[mf], bL[nf]);
                mma_bf16(acc[mf][nf], aL[mf], bH[nf]);
            }
    }

    const int qr = l >> 2, qc = (l & 3) * 2;
    #pragma unroll
    for (int mf = 0; mf < 2; mf++) {
        const int r0 = m0 + wm + mf*16 + qr;
        const int r1 = r0 + 8;
        #pragma unroll
        for (int nf = 0; nf < 8; nf++) {
            const int col = n0 + wn + nf*8 + qc;
            const float b0 = bias[col], b1 = bias[col+1];
            *(float2*)&g_o[(size_t)r0 * C_ + col] =
                make_float2(acc[mf][nf][0] + b0, acc[mf][nf][1] + b1);
            *(float2*)&g_o[(size_t)r1 * C_ + col] =
                make_float2(acc[mf][nf][2] + b0, acc[mf][nf][3] + b1);
        }
    }
}

// ---------------- BN stats ------------------------------------------------
__global__ void stats1_kernel() {
    const int chunk = blockIdx.x;
    const int c = threadIdx.x;
    float s = 0.f, ss = 0.f;
    const float* p = g_o + (size_t)chunk * 64 * C_ + c;
    #pragma unroll 4
    for (int r = 0; r < 64; r++) {
        float v = p[(size_t)r * C_];
        s += v; ss += v * v;
    }
    g_ps[0][chunk][c] = s;
    g_ps[1][chunk][c] = ss;
}

__global__ void stats2_kernel(const float* __restrict__ gamma,
                              const float* __restrict__ beta) {
    const int c = threadIdx.x;
    float s = 0.f, ss = 0.f;
    for (int k = 0; k < 256; k++) { s += g_ps[0][k][c]; ss += g_ps[1][k][c]; }
    const float inv_n = 1.0f / (float)MALL;
    float mean = s * inv_n;
    float var  = ss * inv_n - mean * mean;
    float sc = gamma[c] * rsqrtf(var + EPSbn);
    g_scale[c] = sc;
    g_shift[c] = beta[c] - mean * sc;
}

// ---------------- BN apply + ReLU + residual ------------------------------
__global__ void final_kernel(const float* __restrict__ x, float* __restrict__ out) {
    __shared__ float tile[64][65];
    const int s0 = blockIdx.x * 64;
    const int c0 = blockIdx.y * 64;
    const int b  = blockIdx.z;
    const int t  = threadIdx.x;

    const int lr = t >> 2, lc = (t & 3) * 16;
    #pragma unroll
    for (int q = 0; q < 4; q++) {
        float4 v = *(const float4*)&g_o[(size_t)(b*HW_ + s0 + lr) * C_ + c0 + lc + q*4];
        tile[lr][lc + q*4 + 0] = v.x; tile[lr][lc + q*4 + 1] = v.y;
        tile[lr][lc + q*4 + 2] = v.z; tile[lr][lc + q*4 + 3] = v.w;
    }
    __syncthreads();

    const int cl = t >> 2, sg = (t & 3) * 16;
    const int c = c0 + cl;
    const float sc = g_scale[c], sh = g_shift[c];
    const size_t base = ((size_t)b * C_ + c) * HW_ + s0 + sg;
    #pragma unroll
    for (int q = 0; q < 4; q++) {
        float4 xv = *(const float4*)&x[base + q*4];
        float4 w;
        w.x = fmaxf(tile[sg + q*4 + 0][cl] * sc + sh, 0.f) + xv.x;
        w.y = fmaxf(tile[sg + q*4 + 1][cl] * sc + sh, 0.f) + xv.y;
        w.z = fmaxf(tile[sg + q*4 + 2][cl] * sc + sh, 0.f) + xv.z;
        w.w = fmaxf(tile[sg + q*4 + 3][cl] * sc + sh, 0.f) + xv.w;
        *(float4*)&out[base + q*4] = w;
    }
}

// ---------------- launch ---------------------------------------------------
extern "C" void kernel_launch(void* const* d_in, const int* in_sizes, int n_in,
                              void* d_out, int out_size) {
    const float* x     = (const float*)d_in[0];
    const float* gw    = (const float*)d_in[1];
    const float* gb    = (const float*)d_in[2];
    const float* tw    = (const float*)d_in[3];
    const float* tb    = (const float*)d_in[4];
    const float* pw    = (const float*)d_in[5];
    const float* pb    = (const float*)d_in[6];
    const float* ow    = (const float*)d_in[7];
    const float* ob    = (const float*)d_in[8];
    const float* gamma = (const float*)d_in[9];
    const float* beta  = (const float*)d_in[10];
    float* out = (float*)d_out;

    cudaFuncSetAttribute(attn_fused,  cudaFuncAttributeMaxDynamicSharedMemorySize, ATT_SMEM);
    cudaFuncSetAttribute(outconv_mma, cudaFuncAttributeMaxDynamicSharedMemorySize, 4 * OC_PLANE);

    proj_kernel    <<<dim3(6, 256),   256>>>(x, gw, gb, tw, tb, pw, pb);
    wconv_kernel   <<<dim3(128),      256>>>(ow);
    attn_fused     <<<dim3(64, 4),    128, ATT_SMEM>>>();
    outconv_mma    <<<dim3(2, 128),   256, 4 * OC_PLANE>>>(ob);
    stats1_kernel  <<<dim3(256),      256>>>();
    stats2_kernel  <<<dim3(1),        256>>>(gamma, beta);
    final_kernel   <<<dim3(64, 4, 4), 256>>>(x, out);
}